// round 7
// baseline (speedup 1.0000x reference)
#include <cuda_runtime.h>
#include <cuda_fp16.h>
#include <stdint.h>
#include <math.h>

// ---------------- problem constants ------------------------------------------
#define H_DIM  2048
#define E_NUM  16
#define F_DIM  1408
#define FS_DIM 4096
#define T_NUM  2048   // B*S
#define TOPK   4
#define CAP    2048

// ---------------- GEMM tiling ------------------------------------------------
#define BM 128
#define BN 64
#define BK 64
#define STAGES 4
#define KSTR 72        // A smem row stride (halves)
#define BSTR 72        // B smem row stride (halves), [k][n] layout
#define A_H (BM * KSTR)          // 9216 halves
#define B_H (BK * BSTR)          // 4608 halves
#define STAGE_H (A_H + B_H)      // 13824 halves = 27648 B
#define GM_SMEM (STAGE_H * STAGES * 2)  // 110592 B -> 2 CTAs/SM

// ---------------- static scratch ---------------------------------------------
__device__ __half d_Xg[(size_t)E_NUM * CAP * H_DIM];     // gathered w*x (fp16)
__device__ __half d_xh[(size_t)T_NUM * H_DIM];           // fp16 x (shared expert)
__device__ __half d_g[(size_t)E_NUM * CAP * F_DIM];      // routed gate, then h
__device__ __half d_u[(size_t)E_NUM * CAP * F_DIM];      // routed up
__device__ __half d_gs[(size_t)T_NUM * FS_DIM];          // shared gate, then h
__device__ __half d_us[(size_t)T_NUM * FS_DIM];          // shared up
__device__ float  d_Yr[(size_t)E_NUM * CAP * H_DIM];     // routed down out per slot
__device__ __half d_WgH[(size_t)E_NUM * H_DIM * F_DIM];  // fp16 natural [e][H][F]
__device__ __half d_WuH[(size_t)E_NUM * H_DIM * F_DIM];
__device__ __half d_WdH[(size_t)E_NUM * F_DIM * H_DIM];  // [e][F][H]
__device__ __half d_WgsH[(size_t)H_DIM * FS_DIM];        // [H][FS]
__device__ __half d_WusH[(size_t)H_DIM * FS_DIM];
__device__ __half d_WdsH[(size_t)FS_DIM * H_DIM];        // [FS][H]
__device__ int    d_cnt[E_NUM];
__device__ int    d_t2s[T_NUM * TOPK];
__device__ float  d_t2w[T_NUM * TOPK];

// ---------------- helpers ----------------------------------------------------
__device__ __forceinline__ uint32_t sptr(const void* p) {
    return (uint32_t)__cvta_generic_to_shared(p);
}
__device__ __forceinline__ void cp16(uint32_t dst, const void* src) {
    asm volatile("cp.async.cg.shared.global [%0], [%1], 16;\n" :: "r"(dst), "l"(src));
}
__device__ __forceinline__ void cp16z(uint32_t dst, const void* src, bool pred) {
    int sz = pred ? 16 : 0;
    asm volatile("cp.async.cg.shared.global [%0], [%1], 16, %2;\n" :: "r"(dst), "l"(src), "r"(sz));
}
#define CP_COMMIT asm volatile("cp.async.commit_group;\n" ::: "memory")
#define CP_WAIT2  asm volatile("cp.async.wait_group 2;\n" ::: "memory")

__device__ __forceinline__ void ldm_x4(uint32_t* r, uint32_t addr) {
    asm volatile("ldmatrix.sync.aligned.m8n8.x4.shared.b16 {%0,%1,%2,%3}, [%4];\n"
                 : "=r"(r[0]), "=r"(r[1]), "=r"(r[2]), "=r"(r[3]) : "r"(addr));
}
__device__ __forceinline__ void ldm_x4t(uint32_t* r, uint32_t addr) {
    asm volatile("ldmatrix.sync.aligned.m8n8.x4.trans.shared.b16 {%0,%1,%2,%3}, [%4];\n"
                 : "=r"(r[0]), "=r"(r[1]), "=r"(r[2]), "=r"(r[3]) : "r"(addr));
}
__device__ __forceinline__ void mma16816(float* c, const uint32_t* a, const uint32_t* b) {
    asm volatile(
        "mma.sync.aligned.m16n8k16.row.col.f32.f16.f16.f32 "
        "{%0,%1,%2,%3}, {%4,%5,%6,%7}, {%8,%9}, {%0,%1,%2,%3};\n"
        : "+f"(c[0]), "+f"(c[1]), "+f"(c[2]), "+f"(c[3])
        : "r"(a[0]), "r"(a[1]), "r"(a[2]), "r"(a[3]), "r"(b[0]), "r"(b[1]));
}
__device__ __forceinline__ float silu_f(float g) {
    return g / (1.0f + __expf(-g));
}

// ---------------- kernel: streaming fp32 -> fp16 convert (3 tensors via z) ---
__global__ void convert3_f2h_kernel(const float* __restrict__ i0,
                                    const float* __restrict__ i1,
                                    const float* __restrict__ i2,
                                    __half* __restrict__ o0,
                                    __half* __restrict__ o1,
                                    __half* __restrict__ o2,
                                    size_t n4) {
    const float4* in4;
    uint2* out8;
    if (blockIdx.z == 0)      { in4 = (const float4*)i0; out8 = (uint2*)o0; }
    else if (blockIdx.z == 1) { in4 = (const float4*)i1; out8 = (uint2*)o1; }
    else                      { in4 = (const float4*)i2; out8 = (uint2*)o2; }
    size_t idx = (size_t)blockIdx.x * blockDim.x + threadIdx.x;
    size_t stride = (size_t)gridDim.x * blockDim.x;
    for (size_t i = idx; i < n4; i += stride) {
        float4 v = in4[i];
        union { __half2 h[2]; uint2 u; } r;
        r.h[0] = __floats2half2_rn(v.x, v.y);
        r.h[1] = __floats2half2_rn(v.z, v.w);
        out8[i] = r.u;
    }
}

// ---------------- kernel: zero counters --------------------------------------
__global__ void moe_zero_cnt_kernel(int* cnt) {
    if (threadIdx.x < E_NUM) cnt[threadIdx.x] = 0;
}

// ---------------- kernel: router + softmax + top4 + gather -------------------
__global__ void moe_router_kernel(const float* __restrict__ x,
                                  const float* __restrict__ wr,
                                  __half* __restrict__ xh,
                                  __half* __restrict__ Xg,
                                  int* __restrict__ cnt,
                                  int* __restrict__ t2s,
                                  float* __restrict__ t2w) {
    __shared__ float xs[H_DIM];
    __shared__ float logits[E_NUM];
    __shared__ int   sel_slot[TOPK];
    __shared__ float sel_w[TOPK];

    const int t = blockIdx.x;
    const int tid = threadIdx.x;
    const int lane = tid & 31;
    const int warp = tid >> 5;

    for (int i = tid; i < H_DIM; i += 128) xs[i] = x[(size_t)t * H_DIM + i];
    __syncthreads();

    for (int e = warp * 4; e < warp * 4 + 4; e++) {
        float s = 0.f;
        const float* wre = wr + (size_t)e * H_DIM;
        for (int h = lane; h < H_DIM; h += 32) s += xs[h] * wre[h];
        #pragma unroll
        for (int off = 16; off; off >>= 1) s += __shfl_xor_sync(0xffffffffu, s, off);
        if (lane == 0) logits[e] = s;
    }
    __syncthreads();

    if (tid == 0) {
        float p[E_NUM];
        float mx = -1e30f;
        #pragma unroll
        for (int e = 0; e < E_NUM; e++) mx = fmaxf(mx, logits[e]);
        #pragma unroll
        for (int e = 0; e < E_NUM; e++) p[e] = expf(logits[e] - mx);
        float tw = 0.f;
        for (int j = 0; j < TOPK; j++) {
            int am = 0; float bv = -1.f;
            #pragma unroll
            for (int e = 0; e < E_NUM; e++) { if (p[e] > bv) { bv = p[e]; am = e; } }
            int pos = atomicAdd(&cnt[am], 1);
            sel_slot[j] = am * CAP + pos;
            sel_w[j]    = bv;
            tw += bv;
            p[am] = -2.f;
        }
        float inv = 1.f / tw;
        for (int j = 0; j < TOPK; j++) {
            float w = sel_w[j] * inv;
            sel_w[j] = w;
            t2s[t * TOPK + j] = sel_slot[j];
            t2w[t * TOPK + j] = w;
        }
    }
    __syncthreads();

    const int s0 = sel_slot[0], s1 = sel_slot[1], s2 = sel_slot[2], s3 = sel_slot[3];
    const float w0 = sel_w[0], w1 = sel_w[1], w2 = sel_w[2], w3 = sel_w[3];
    for (int i = tid; i < H_DIM; i += 128) {
        float v = xs[i];
        xh[(size_t)t * H_DIM + i]  = __float2half(v);
        Xg[(size_t)s0 * H_DIM + i] = __float2half(w0 * v);
        Xg[(size_t)s1 * H_DIM + i] = __float2half(w1 * v);
        Xg[(size_t)s2 * H_DIM + i] = __float2half(w2 * v);
        Xg[(size_t)s3 * H_DIM + i] = __float2half(w3 * v);
    }
}

// ---------------- unified GEMM: C(128m x 64n) = A[m][k] * B[k][n] ------------
// MODE 0: fp16 store; MODE 1: fp32 store.
// 256 threads (8 warps: 4m x 2n, warp 32x32), 4-stage cp.async, frag dbl-buffer.
template <int MODE>
__global__ __launch_bounds__(256, 2)
void gemm_kernel(const __half* __restrict__ Abase,
                 const __half* __restrict__ Bbase,
                 void* __restrict__ OutBase,
                 const int* __restrict__ cnt,
                 int K, int N,
                 size_t aBatch, size_t bBatch, size_t oBatch) {
    const int e = blockIdx.z;
    const int M = cnt ? cnt[e] : T_NUM;
    const int m0 = blockIdx.x * BM;
    if (m0 >= M) return;
    const int n0 = blockIdx.y * BN;
    const __half* A = Abase + (size_t)e * aBatch;
    const __half* B = Bbase + (size_t)e * bBatch;

    extern __shared__ __half smem[];
    const int tid = threadIdx.x;
    const int lane = tid & 31;
    const int warp = tid >> 5;
    const int wm = warp >> 1, wn = warp & 1;

    auto load_stage = [&](int s, int k0) {
        __half* As = smem + s * STAGE_H;
        __half* Bs = As + A_H;
        int c = tid;
        #pragma unroll
        for (int i = 0; i < 4; i++, c += 256) {        // A: 128 rows x 8 chunks
            int row = c >> 3, ch = c & 7;
            cp16z(sptr(As + row * KSTR + ch * 8),
                  A + (size_t)(m0 + row) * K + k0 + ch * 8, (m0 + row) < M);
        }
        c = tid;
        #pragma unroll
        for (int i = 0; i < 2; i++, c += 256) {        // B: 64 k-rows x 8 chunks
            int row = c >> 3, ch = c & 7;
            cp16(sptr(Bs + row * BSTR + ch * 8),
                 B + (size_t)(k0 + row) * N + n0 + ch * 8);
        }
    };

    float acc[2][4][4];
    #pragma unroll
    for (int a = 0; a < 2; a++)
        #pragma unroll
        for (int b = 0; b < 4; b++)
            #pragma unroll
            for (int c = 0; c < 4; c++) acc[a][b][c] = 0.f;

    const int KT = K / BK;
    load_stage(0, 0);      CP_COMMIT;
    load_stage(1, BK);     CP_COMMIT;
    load_stage(2, 2 * BK); CP_COMMIT;

    const int t8 = lane >> 3, r8 = lane & 7;
    const int aRow = wm * 32 + (t8 & 1) * 8 + r8;   // + mf*16
    const int aCol = (t8 >> 1) * 8;                 // + kk
    const int bRowT = (t8 & 1) * 8 + r8;            // + kk (k index)
    const int bColT = wn * 32 + (t8 >> 1) * 8;      // + p*16 (n index)

    uint32_t af[2][2][4], bf[2][2][4];

    auto load_frag = [&](const __half* As, const __half* Bs, int kk, int buf) {
        ldm_x4(af[buf][0], sptr(As + (aRow)      * KSTR + kk + aCol));
        ldm_x4(af[buf][1], sptr(As + (aRow + 16) * KSTR + kk + aCol));
        uint32_t boff = (kk + bRowT) * BSTR + bColT;
        ldm_x4t(bf[buf][0], sptr(Bs + boff));
        ldm_x4t(bf[buf][1], sptr(Bs + boff + 16));
    };
    auto do_mma = [&](int buf) {
        #pragma unroll
        for (int p = 0; p < 2; p++) {
            #pragma unroll
            for (int h = 0; h < 2; h++) {
                int nf = p * 2 + h;
                mma16816(acc[0][nf], af[buf][0], &bf[buf][p][h * 2]);
                mma16816(acc[1][nf], af[buf][1], &bf[buf][p][h * 2]);
            }
        }
    };

    for (int it = 0; it < KT; ++it) {
        CP_WAIT2;
        __syncthreads();
        int pf = it + STAGES - 1;
        if (pf < KT) load_stage(pf % STAGES, pf * BK);
        CP_COMMIT;

        const __half* As = smem + (it % STAGES) * STAGE_H;
        const __half* Bs = As + A_H;

        load_frag(As, Bs, 0, 0);
        #pragma unroll
        for (int k4 = 0; k4 < 4; k4++) {
            int cur = k4 & 1;
            if (k4 < 3) load_frag(As, Bs, (k4 + 1) * 16, cur ^ 1);
            do_mma(cur);
        }
    }

    // epilogue
    #pragma unroll
    for (int mf = 0; mf < 2; mf++) {
        #pragma unroll
        for (int nf = 0; nf < 4; nf++) {
            int row0 = m0 + wm * 32 + mf * 16 + (lane >> 2);
            int col  = n0 + wn * 32 + (nf >> 1) * 16 + (nf & 1) * 8 + (lane & 3) * 2;
            float* c = acc[mf][nf];
            if (MODE == 0) {
                __half* OutH = (__half*)OutBase + (size_t)e * oBatch;
                if (row0 < M)
                    *(__half2*)&OutH[(size_t)row0 * N + col] = __floats2half2_rn(c[0], c[1]);
                if (row0 + 8 < M)
                    *(__half2*)&OutH[(size_t)(row0 + 8) * N + col] = __floats2half2_rn(c[2], c[3]);
            } else {
                float* OutF = (float*)OutBase + (size_t)e * oBatch;
                if (row0 < M) {
                    float2 v = {c[0], c[1]};
                    *(float2*)&OutF[(size_t)row0 * N + col] = v;
                }
                if (row0 + 8 < M) {
                    float2 v = {c[2], c[3]};
                    *(float2*)&OutF[(size_t)(row0 + 8) * N + col] = v;
                }
            }
        }
    }
}

// ---------------- kernel: h = silu(g) * u (in-place into g) ------------------
__global__ void silu_mul_kernel(__half* __restrict__ g,
                                const __half* __restrict__ u,
                                const int* __restrict__ cnt,
                                int Fdim, int perE) {
    const int row = blockIdx.x;
    if (cnt) {
        int e = row / perE;
        if ((row - e * perE) >= cnt[e]) return;
    }
    __half2* gp = (__half2*)(g + (size_t)row * Fdim);
    const __half2* up = (const __half2*)(u + (size_t)row * Fdim);
    for (int i = threadIdx.x; i < Fdim / 2; i += blockDim.x) {
        float2 gv = __half22float2(gp[i]);
        float2 uv = __half22float2(up[i]);
        gp[i] = __floats2half2_rn(silu_f(gv.x) * uv.x, silu_f(gv.y) * uv.y);
    }
}

// ---------------- kernel: combine routed contributions -----------------------
__global__ void moe_combine_kernel(float* __restrict__ out,
                                   const float* __restrict__ Yr,
                                   const int* __restrict__ t2s,
                                   const float* __restrict__ t2w) {
    const int t = blockIdx.x;
    const int s0 = t2s[t * TOPK + 0], s1 = t2s[t * TOPK + 1];
    const int s2 = t2s[t * TOPK + 2], s3 = t2s[t * TOPK + 3];
    const float w0 = t2w[t * TOPK + 0], w1 = t2w[t * TOPK + 1];
    const float w2 = t2w[t * TOPK + 2], w3 = t2w[t * TOPK + 3];
    float4* o = (float4*)(out + (size_t)t * H_DIM);
    const float4* y0 = (const float4*)(Yr + (size_t)s0 * H_DIM);
    const float4* y1 = (const float4*)(Yr + (size_t)s1 * H_DIM);
    const float4* y2 = (const float4*)(Yr + (size_t)s2 * H_DIM);
    const float4* y3 = (const float4*)(Yr + (size_t)s3 * H_DIM);
    for (int i = threadIdx.x; i < H_DIM / 4; i += 256) {
        float4 v = o[i];
        float4 a0 = y0[i], a1 = y1[i], a2 = y2[i], a3 = y3[i];
        v.x += w0 * a0.x + w1 * a1.x + w2 * a2.x + w3 * a3.x;
        v.y += w0 * a0.y + w1 * a1.y + w2 * a2.y + w3 * a3.y;
        v.z += w0 * a0.z + w1 * a1.z + w2 * a2.z + w3 * a3.z;
        v.w += w0 * a0.w + w1 * a1.w + w2 * a2.w + w3 * a3.w;
        o[i] = v;
    }
}

// ---------------- launch -----------------------------------------------------
extern "C" void kernel_launch(void* const* d_in, const int* in_sizes, int n_in,
                              void* d_out, int out_size) {
    const float* x   = (const float*)d_in[0];
    const float* wr  = (const float*)d_in[1];
    const float* Wg  = (const float*)d_in[2];
    const float* Wu  = (const float*)d_in[3];
    const float* Wd  = (const float*)d_in[4];
    const float* Wgs = (const float*)d_in[5];
    const float* Wus = (const float*)d_in[6];
    const float* Wds = (const float*)d_in[7];
    float* out = (float*)d_out;

    __half *Xg, *xh, *g, *u, *gs, *us, *WgH, *WuH, *WdH, *WgsH, *WusH, *WdsH;
    float *Yr, *t2w;
    int *cnt, *t2s;
    cudaGetSymbolAddress((void**)&Xg,   d_Xg);
    cudaGetSymbolAddress((void**)&xh,   d_xh);
    cudaGetSymbolAddress((void**)&g,    d_g);
    cudaGetSymbolAddress((void**)&u,    d_u);
    cudaGetSymbolAddress((void**)&gs,   d_gs);
    cudaGetSymbolAddress((void**)&us,   d_us);
    cudaGetSymbolAddress((void**)&Yr,   d_Yr);
    cudaGetSymbolAddress((void**)&WgH,  d_WgH);
    cudaGetSymbolAddress((void**)&WuH,  d_WuH);
    cudaGetSymbolAddress((void**)&WdH,  d_WdH);
    cudaGetSymbolAddress((void**)&WgsH, d_WgsH);
    cudaGetSymbolAddress((void**)&WusH, d_WusH);
    cudaGetSymbolAddress((void**)&WdsH, d_WdsH);
    cudaGetSymbolAddress((void**)&cnt,  d_cnt);
    cudaGetSymbolAddress((void**)&t2s,  d_t2s);
    cudaGetSymbolAddress((void**)&t2w,  d_t2w);

    cudaFuncSetAttribute(gemm_kernel<0>, cudaFuncAttributeMaxDynamicSharedMemorySize, GM_SMEM);
    cudaFuncSetAttribute(gemm_kernel<1>, cudaFuncAttributeMaxDynamicSharedMemorySize, GM_SMEM);

    // weight converts (fp32 -> fp16, natural [K][N] layouts)
    size_t nE = (size_t)E_NUM * H_DIM * F_DIM / 4;
    size_t nS = (size_t)H_DIM * FS_DIM / 4;
    convert3_f2h_kernel<<<dim3(4096, 1, 3), 256>>>(Wg, Wu, Wd, WgH, WuH, WdH, nE);
    convert3_f2h_kernel<<<dim3(2048, 1, 3), 256>>>(Wgs, Wus, Wds, WgsH, WusH, WdsH, nS);

    moe_zero_cnt_kernel<<<1, 32>>>(cnt);
    moe_router_kernel<<<T_NUM, 128>>>(x, wr, xh, Xg, cnt, t2s, t2w);

    const size_t aR = (size_t)CAP * H_DIM, bR = (size_t)H_DIM * F_DIM, oR = (size_t)CAP * F_DIM;

    // routed gate / up
    gemm_kernel<0><<<dim3(CAP / BM, F_DIM / BN, E_NUM), 256, GM_SMEM>>>(
        Xg, WgH, g, cnt, H_DIM, F_DIM, aR, bR, oR);
    gemm_kernel<0><<<dim3(CAP / BM, F_DIM / BN, E_NUM), 256, GM_SMEM>>>(
        Xg, WuH, u, cnt, H_DIM, F_DIM, aR, bR, oR);
    // shared gate / up
    gemm_kernel<0><<<dim3(T_NUM / BM, FS_DIM / BN, 1), 256, GM_SMEM>>>(
        xh, WgsH, gs, nullptr, H_DIM, FS_DIM, 0, 0, 0);
    gemm_kernel<0><<<dim3(T_NUM / BM, FS_DIM / BN, 1), 256, GM_SMEM>>>(
        xh, WusH, us, nullptr, H_DIM, FS_DIM, 0, 0, 0);

    // silu * u (in place into g / gs)
    silu_mul_kernel<<<E_NUM * CAP, 128>>>(g, u, cnt, F_DIM, CAP);
    silu_mul_kernel<<<T_NUM, 128>>>(gs, us, nullptr, FS_DIM, T_NUM);

    // down: shared writes out directly; routed writes Yr slots
    gemm_kernel<1><<<dim3(T_NUM / BM, H_DIM / BN, 1), 256, GM_SMEM>>>(
        gs, WdsH, out, nullptr, FS_DIM, H_DIM, 0, 0, 0);
    gemm_kernel<1><<<dim3(CAP / BM, H_DIM / BN, E_NUM), 256, GM_SMEM>>>(
        g, WdH, Yr, cnt, F_DIM, H_DIM,
        (size_t)CAP * F_DIM, (size_t)F_DIM * H_DIM, (size_t)CAP * H_DIM);

    moe_combine_kernel<<<T_NUM, 256>>>(out, Yr, t2s, t2w);
}

// round 8
// speedup vs baseline: 1.1344x; 1.1344x over previous
#include <cuda_runtime.h>
#include <cuda_fp16.h>
#include <stdint.h>
#include <math.h>

// ---------------- problem constants ------------------------------------------
#define H_DIM  2048
#define E_NUM  16
#define F_DIM  1408
#define FS_DIM 4096
#define T_NUM  2048   // B*S
#define TOPK   4
#define CAP    2048

// ---------------- GEMM tiling: 256m x 128n, BK=64, 512 threads ----------------
#define BM 256
#define BN 128
#define BK 64
#define STAGES 4
#define KSTR 72        // A smem row stride (halves), [m][k]
#define BSTR 136       // B smem row stride (halves), [k][n] natural
#define A_H (BM * KSTR)          // 18432 halves
#define B_H (BK * BSTR)          // 8704 halves
#define STAGE_H (A_H + B_H)      // 27136 halves = 54272 B
#define GM_SMEM (STAGE_H * STAGES * 2)  // 217088 B -> 1 CTA/SM

// ---------------- static scratch ---------------------------------------------
__device__ __half d_Xg[(size_t)E_NUM * CAP * H_DIM];     // gathered w*x (fp16)
__device__ __half d_xh[(size_t)T_NUM * H_DIM];           // fp16 x (shared expert)
__device__ __half d_g[(size_t)E_NUM * CAP * F_DIM];      // routed gate, then h
__device__ __half d_u[(size_t)E_NUM * CAP * F_DIM];      // routed up
__device__ __half d_gs[(size_t)T_NUM * FS_DIM];          // shared gate, then h
__device__ __half d_us[(size_t)T_NUM * FS_DIM];          // shared up
__device__ float  d_Yr[(size_t)E_NUM * CAP * H_DIM];     // routed down out per slot
__device__ __half d_WgH[(size_t)E_NUM * H_DIM * F_DIM];  // fp16 natural [e][H][F]
__device__ __half d_WuH[(size_t)E_NUM * H_DIM * F_DIM];
__device__ __half d_WdH[(size_t)E_NUM * F_DIM * H_DIM];  // [e][F][H]
__device__ __half d_WgsH[(size_t)H_DIM * FS_DIM];        // [H][FS]
__device__ __half d_WusH[(size_t)H_DIM * FS_DIM];
__device__ __half d_WdsH[(size_t)FS_DIM * H_DIM];        // [FS][H]
__device__ int    d_cnt[E_NUM];
__device__ int    d_t2s[T_NUM * TOPK];
__device__ float  d_t2w[T_NUM * TOPK];

// ---------------- helpers ----------------------------------------------------
__device__ __forceinline__ uint32_t sptr(const void* p) {
    return (uint32_t)__cvta_generic_to_shared(p);
}
__device__ __forceinline__ void cp16(uint32_t dst, const void* src) {
    asm volatile("cp.async.cg.shared.global [%0], [%1], 16;\n" :: "r"(dst), "l"(src));
}
__device__ __forceinline__ void cp16z(uint32_t dst, const void* src, bool pred) {
    int sz = pred ? 16 : 0;
    asm volatile("cp.async.cg.shared.global [%0], [%1], 16, %2;\n" :: "r"(dst), "l"(src), "r"(sz));
}
#define CP_COMMIT asm volatile("cp.async.commit_group;\n" ::: "memory")
#define CP_WAIT2  asm volatile("cp.async.wait_group 2;\n" ::: "memory")

__device__ __forceinline__ void ldm_x4(uint32_t* r, uint32_t addr) {
    asm volatile("ldmatrix.sync.aligned.m8n8.x4.shared.b16 {%0,%1,%2,%3}, [%4];\n"
                 : "=r"(r[0]), "=r"(r[1]), "=r"(r[2]), "=r"(r[3]) : "r"(addr));
}
__device__ __forceinline__ void ldm_x4t(uint32_t* r, uint32_t addr) {
    asm volatile("ldmatrix.sync.aligned.m8n8.x4.trans.shared.b16 {%0,%1,%2,%3}, [%4];\n"
                 : "=r"(r[0]), "=r"(r[1]), "=r"(r[2]), "=r"(r[3]) : "r"(addr));
}
__device__ __forceinline__ void mma16816(float* c, const uint32_t* a, const uint32_t* b) {
    asm volatile(
        "mma.sync.aligned.m16n8k16.row.col.f32.f16.f16.f32 "
        "{%0,%1,%2,%3}, {%4,%5,%6,%7}, {%8,%9}, {%0,%1,%2,%3};\n"
        : "+f"(c[0]), "+f"(c[1]), "+f"(c[2]), "+f"(c[3])
        : "r"(a[0]), "r"(a[1]), "r"(a[2]), "r"(a[3]), "r"(b[0]), "r"(b[1]));
}
__device__ __forceinline__ float silu_f(float g) {
    return g / (1.0f + __expf(-g));
}

// ---------------- kernel: streaming fp32 -> fp16 convert (3 tensors via z) ---
__global__ void convert3_f2h_kernel(const float* __restrict__ i0,
                                    const float* __restrict__ i1,
                                    const float* __restrict__ i2,
                                    __half* __restrict__ o0,
                                    __half* __restrict__ o1,
                                    __half* __restrict__ o2,
                                    size_t n4) {
    const float4* in4;
    uint2* out8;
    if (blockIdx.z == 0)      { in4 = (const float4*)i0; out8 = (uint2*)o0; }
    else if (blockIdx.z == 1) { in4 = (const float4*)i1; out8 = (uint2*)o1; }
    else                      { in4 = (const float4*)i2; out8 = (uint2*)o2; }
    size_t idx = (size_t)blockIdx.x * blockDim.x + threadIdx.x;
    size_t stride = (size_t)gridDim.x * blockDim.x;
    for (size_t i = idx; i < n4; i += stride) {
        float4 v = in4[i];
        union { __half2 h[2]; uint2 u; } r;
        r.h[0] = __floats2half2_rn(v.x, v.y);
        r.h[1] = __floats2half2_rn(v.z, v.w);
        out8[i] = r.u;
    }
}

// ---------------- kernel: zero counters --------------------------------------
__global__ void moe_zero_cnt_kernel(int* cnt) {
    if (threadIdx.x < E_NUM) cnt[threadIdx.x] = 0;
}

// ---------------- kernel: router + softmax + top4 + gather -------------------
__global__ void moe_router_kernel(const float* __restrict__ x,
                                  const float* __restrict__ wr,
                                  __half* __restrict__ xh,
                                  __half* __restrict__ Xg,
                                  int* __restrict__ cnt,
                                  int* __restrict__ t2s,
                                  float* __restrict__ t2w) {
    __shared__ float xs[H_DIM];
    __shared__ float logits[E_NUM];
    __shared__ int   sel_slot[TOPK];
    __shared__ float sel_w[TOPK];

    const int t = blockIdx.x;
    const int tid = threadIdx.x;
    const int lane = tid & 31;
    const int warp = tid >> 5;

    for (int i = tid; i < H_DIM; i += 128) xs[i] = x[(size_t)t * H_DIM + i];
    __syncthreads();

    for (int e = warp * 4; e < warp * 4 + 4; e++) {
        float s = 0.f;
        const float* wre = wr + (size_t)e * H_DIM;
        for (int h = lane; h < H_DIM; h += 32) s += xs[h] * wre[h];
        #pragma unroll
        for (int off = 16; off; off >>= 1) s += __shfl_xor_sync(0xffffffffu, s, off);
        if (lane == 0) logits[e] = s;
    }
    __syncthreads();

    if (tid == 0) {
        float p[E_NUM];
        float mx = -1e30f;
        #pragma unroll
        for (int e = 0; e < E_NUM; e++) mx = fmaxf(mx, logits[e]);
        #pragma unroll
        for (int e = 0; e < E_NUM; e++) p[e] = expf(logits[e] - mx);
        float tw = 0.f;
        for (int j = 0; j < TOPK; j++) {
            int am = 0; float bv = -1.f;
            #pragma unroll
            for (int e = 0; e < E_NUM; e++) { if (p[e] > bv) { bv = p[e]; am = e; } }
            int pos = atomicAdd(&cnt[am], 1);
            sel_slot[j] = am * CAP + pos;
            sel_w[j]    = bv;
            tw += bv;
            p[am] = -2.f;
        }
        float inv = 1.f / tw;
        for (int j = 0; j < TOPK; j++) {
            float w = sel_w[j] * inv;
            sel_w[j] = w;
            t2s[t * TOPK + j] = sel_slot[j];
            t2w[t * TOPK + j] = w;
        }
    }
    __syncthreads();

    const int s0 = sel_slot[0], s1 = sel_slot[1], s2 = sel_slot[2], s3 = sel_slot[3];
    const float w0 = sel_w[0], w1 = sel_w[1], w2 = sel_w[2], w3 = sel_w[3];
    for (int i = tid; i < H_DIM; i += 128) {
        float v = xs[i];
        xh[(size_t)t * H_DIM + i]  = __float2half(v);
        Xg[(size_t)s0 * H_DIM + i] = __float2half(w0 * v);
        Xg[(size_t)s1 * H_DIM + i] = __float2half(w1 * v);
        Xg[(size_t)s2 * H_DIM + i] = __float2half(w2 * v);
        Xg[(size_t)s3 * H_DIM + i] = __float2half(w3 * v);
    }
}

// ---------------- unified GEMM: C(256m x 128n) = A[m][k] * B[k][n] -----------
// MODE 0: fp16 store; MODE 1: fp32 store.
// 512 threads (16 warps: 4m x 4n, warp 64x32), 4-stage cp.async.
template <int MODE>
__global__ __launch_bounds__(512, 1)
void gemm_kernel(const __half* __restrict__ Abase,
                 const __half* __restrict__ Bbase,
                 void* __restrict__ OutBase,
                 const int* __restrict__ cnt,
                 int K, int N,
                 size_t aBatch, size_t bBatch, size_t oBatch) {
    const int e = blockIdx.z;
    const int M = cnt ? cnt[e] : T_NUM;
    const int m0 = blockIdx.x * BM;
    if (m0 >= M) return;
    const int n0 = blockIdx.y * BN;
    const __half* A = Abase + (size_t)e * aBatch;
    const __half* B = Bbase + (size_t)e * bBatch;

    extern __shared__ __half smem[];
    const int tid = threadIdx.x;
    const int lane = tid & 31;
    const int warp = tid >> 5;
    const int wm = warp >> 2, wn = warp & 3;

    auto load_stage = [&](int s, int k0) {
        __half* As = smem + s * STAGE_H;
        __half* Bs = As + A_H;
        int c = tid;
        #pragma unroll
        for (int i = 0; i < 4; i++, c += 512) {        // A: 256 rows x 8 chunks
            int row = c >> 3, ch = c & 7;
            cp16z(sptr(As + row * KSTR + ch * 8),
                  A + (size_t)(m0 + row) * K + k0 + ch * 8, (m0 + row) < M);
        }
        c = tid;
        #pragma unroll
        for (int i = 0; i < 2; i++, c += 512) {        // B: 64 k-rows x 16 chunks
            int row = c >> 4, ch = c & 15;
            cp16(sptr(Bs + row * BSTR + ch * 8),
                 B + (size_t)(k0 + row) * N + n0 + ch * 8);
        }
    };

    float acc[4][4][4];
    #pragma unroll
    for (int a = 0; a < 4; a++)
        #pragma unroll
        for (int b = 0; b < 4; b++)
            #pragma unroll
            for (int c = 0; c < 4; c++) acc[a][b][c] = 0.f;

    const int KT = K / BK;
    load_stage(0, 0);      CP_COMMIT;
    load_stage(1, BK);     CP_COMMIT;
    load_stage(2, 2 * BK); CP_COMMIT;

    const int t8 = lane >> 3, r8 = lane & 7;
    const int aRow = wm * 64 + (t8 & 1) * 8 + r8;   // + mf*16
    const int aCol = (t8 >> 1) * 8;                 // + kk
    const int bRowT = (t8 & 1) * 8 + r8;            // + kk (k index)
    const int bColT = wn * 32 + (t8 >> 1) * 8;      // + p*16 (n index)

    for (int it = 0; it < KT; ++it) {
        CP_WAIT2;
        __syncthreads();
        int pf = it + STAGES - 1;
        if (pf < KT) load_stage(pf % STAGES, pf * BK);
        CP_COMMIT;

        const __half* As = smem + (it % STAGES) * STAGE_H;
        const __half* Bs = As + A_H;

        #pragma unroll
        for (int kk = 0; kk < BK; kk += 16) {
            uint32_t a[4][4];
            #pragma unroll
            for (int mf = 0; mf < 4; mf++)
                ldm_x4(a[mf], sptr(As + (aRow + mf * 16) * KSTR + kk + aCol));
            #pragma unroll
            for (int p = 0; p < 2; p++) {
                uint32_t b[4];
                ldm_x4t(b, sptr(Bs + (kk + bRowT) * BSTR + bColT + p * 16));
                #pragma unroll
                for (int h = 0; h < 2; h++) {
                    int nf = p * 2 + h;
                    #pragma unroll
                    for (int mf = 0; mf < 4; mf++)
                        mma16816(acc[mf][nf], a[mf], &b[h * 2]);
                }
            }
        }
    }

    // epilogue
    #pragma unroll
    for (int mf = 0; mf < 4; mf++) {
        #pragma unroll
        for (int nf = 0; nf < 4; nf++) {
            int row0 = m0 + wm * 64 + mf * 16 + (lane >> 2);
            int col  = n0 + wn * 32 + (nf >> 1) * 16 + (nf & 1) * 8 + (lane & 3) * 2;
            float* c = acc[mf][nf];
            if (MODE == 0) {
                __half* OutH = (__half*)OutBase + (size_t)e * oBatch;
                if (row0 < M)
                    *(__half2*)&OutH[(size_t)row0 * N + col] = __floats2half2_rn(c[0], c[1]);
                if (row0 + 8 < M)
                    *(__half2*)&OutH[(size_t)(row0 + 8) * N + col] = __floats2half2_rn(c[2], c[3]);
            } else {
                float* OutF = (float*)OutBase + (size_t)e * oBatch;
                if (row0 < M) {
                    float2 v = {c[0], c[1]};
                    *(float2*)&OutF[(size_t)row0 * N + col] = v;
                }
                if (row0 + 8 < M) {
                    float2 v = {c[2], c[3]};
                    *(float2*)&OutF[(size_t)(row0 + 8) * N + col] = v;
                }
            }
        }
    }
}

// ---------------- kernel: h = silu(g) * u (in-place into g) ------------------
__global__ void silu_mul_kernel(__half* __restrict__ g,
                                const __half* __restrict__ u,
                                const int* __restrict__ cnt,
                                int Fdim, int perE) {
    const int row = blockIdx.x;
    if (cnt) {
        int e = row / perE;
        if ((row - e * perE) >= cnt[e]) return;
    }
    __half2* gp = (__half2*)(g + (size_t)row * Fdim);
    const __half2* up = (const __half2*)(u + (size_t)row * Fdim);
    for (int i = threadIdx.x; i < Fdim / 2; i += blockDim.x) {
        float2 gv = __half22float2(gp[i]);
        float2 uv = __half22float2(up[i]);
        gp[i] = __floats2half2_rn(silu_f(gv.x) * uv.x, silu_f(gv.y) * uv.y);
    }
}

// ---------------- kernel: combine routed contributions -----------------------
__global__ void moe_combine_kernel(float* __restrict__ out,
                                   const float* __restrict__ Yr,
                                   const int* __restrict__ t2s,
                                   const float* __restrict__ t2w) {
    const int t = blockIdx.x;
    const int s0 = t2s[t * TOPK + 0], s1 = t2s[t * TOPK + 1];
    const int s2 = t2s[t * TOPK + 2], s3 = t2s[t * TOPK + 3];
    const float w0 = t2w[t * TOPK + 0], w1 = t2w[t * TOPK + 1];
    const float w2 = t2w[t * TOPK + 2], w3 = t2w[t * TOPK + 3];
    float4* o = (float4*)(out + (size_t)t * H_DIM);
    const float4* y0 = (const float4*)(Yr + (size_t)s0 * H_DIM);
    const float4* y1 = (const float4*)(Yr + (size_t)s1 * H_DIM);
    const float4* y2 = (const float4*)(Yr + (size_t)s2 * H_DIM);
    const float4* y3 = (const float4*)(Yr + (size_t)s3 * H_DIM);
    for (int i = threadIdx.x; i < H_DIM / 4; i += 256) {
        float4 v = o[i];
        float4 a0 = y0[i], a1 = y1[i], a2 = y2[i], a3 = y3[i];
        v.x += w0 * a0.x + w1 * a1.x + w2 * a2.x + w3 * a3.x;
        v.y += w0 * a0.y + w1 * a1.y + w2 * a2.y + w3 * a3.y;
        v.z += w0 * a0.z + w1 * a1.z + w2 * a2.z + w3 * a3.z;
        v.w += w0 * a0.w + w1 * a1.w + w2 * a2.w + w3 * a3.w;
        o[i] = v;
    }
}

// ---------------- launch -----------------------------------------------------
extern "C" void kernel_launch(void* const* d_in, const int* in_sizes, int n_in,
                              void* d_out, int out_size) {
    const float* x   = (const float*)d_in[0];
    const float* wr  = (const float*)d_in[1];
    const float* Wg  = (const float*)d_in[2];
    const float* Wu  = (const float*)d_in[3];
    const float* Wd  = (const float*)d_in[4];
    const float* Wgs = (const float*)d_in[5];
    const float* Wus = (const float*)d_in[6];
    const float* Wds = (const float*)d_in[7];
    float* out = (float*)d_out;

    __half *Xg, *xh, *g, *u, *gs, *us, *WgH, *WuH, *WdH, *WgsH, *WusH, *WdsH;
    float *Yr, *t2w;
    int *cnt, *t2s;
    cudaGetSymbolAddress((void**)&Xg,   d_Xg);
    cudaGetSymbolAddress((void**)&xh,   d_xh);
    cudaGetSymbolAddress((void**)&g,    d_g);
    cudaGetSymbolAddress((void**)&u,    d_u);
    cudaGetSymbolAddress((void**)&gs,   d_gs);
    cudaGetSymbolAddress((void**)&us,   d_us);
    cudaGetSymbolAddress((void**)&Yr,   d_Yr);
    cudaGetSymbolAddress((void**)&WgH,  d_WgH);
    cudaGetSymbolAddress((void**)&WuH,  d_WuH);
    cudaGetSymbolAddress((void**)&WdH,  d_WdH);
    cudaGetSymbolAddress((void**)&WgsH, d_WgsH);
    cudaGetSymbolAddress((void**)&WusH, d_WusH);
    cudaGetSymbolAddress((void**)&WdsH, d_WdsH);
    cudaGetSymbolAddress((void**)&cnt,  d_cnt);
    cudaGetSymbolAddress((void**)&t2s,  d_t2s);
    cudaGetSymbolAddress((void**)&t2w,  d_t2w);

    cudaFuncSetAttribute(gemm_kernel<0>, cudaFuncAttributeMaxDynamicSharedMemorySize, GM_SMEM);
    cudaFuncSetAttribute(gemm_kernel<1>, cudaFuncAttributeMaxDynamicSharedMemorySize, GM_SMEM);

    // weight converts (fp32 -> fp16, natural [K][N] layouts)
    size_t nE = (size_t)E_NUM * H_DIM * F_DIM / 4;
    size_t nS = (size_t)H_DIM * FS_DIM / 4;
    convert3_f2h_kernel<<<dim3(4096, 1, 3), 256>>>(Wg, Wu, Wd, WgH, WuH, WdH, nE);
    convert3_f2h_kernel<<<dim3(2048, 1, 3), 256>>>(Wgs, Wus, Wds, WgsH, WusH, WdsH, nS);

    moe_zero_cnt_kernel<<<1, 32>>>(cnt);
    moe_router_kernel<<<T_NUM, 128>>>(x, wr, xh, Xg, cnt, t2s, t2w);

    const size_t aR = (size_t)CAP * H_DIM, bR = (size_t)H_DIM * F_DIM, oR = (size_t)CAP * F_DIM;

    // routed gate / up
    gemm_kernel<0><<<dim3(CAP / BM, F_DIM / BN, E_NUM), 512, GM_SMEM>>>(
        Xg, WgH, g, cnt, H_DIM, F_DIM, aR, bR, oR);
    gemm_kernel<0><<<dim3(CAP / BM, F_DIM / BN, E_NUM), 512, GM_SMEM>>>(
        Xg, WuH, u, cnt, H_DIM, F_DIM, aR, bR, oR);
    // shared gate / up
    gemm_kernel<0><<<dim3(T_NUM / BM, FS_DIM / BN, 1), 512, GM_SMEM>>>(
        xh, WgsH, gs, nullptr, H_DIM, FS_DIM, 0, 0, 0);
    gemm_kernel<0><<<dim3(T_NUM / BM, FS_DIM / BN, 1), 512, GM_SMEM>>>(
        xh, WusH, us, nullptr, H_DIM, FS_DIM, 0, 0, 0);

    // silu * u (in place into g / gs)
    silu_mul_kernel<<<E_NUM * CAP, 128>>>(g, u, cnt, F_DIM, CAP);
    silu_mul_kernel<<<T_NUM, 128>>>(gs, us, nullptr, FS_DIM, T_NUM);

    // down: shared writes out directly; routed writes Yr slots
    gemm_kernel<1><<<dim3(T_NUM / BM, H_DIM / BN, 1), 512, GM_SMEM>>>(
        gs, WdsH, out, nullptr, FS_DIM, H_DIM, 0, 0, 0);
    gemm_kernel<1><<<dim3(CAP / BM, H_DIM / BN, E_NUM), 512, GM_SMEM>>>(
        g, WdH, Yr, cnt, F_DIM, H_DIM,
        (size_t)CAP * F_DIM, (size_t)F_DIM * H_DIM, (size_t)CAP * H_DIM);

    moe_combine_kernel<<<T_NUM, 256>>>(out, Yr, t2s, t2w);
}